// round 11
// baseline (speedup 1.0000x reference)
#include <cuda_runtime.h>

// HausdorffDTLoss: B=4, C=2, H=W=256, ALPHA=2.
// Matches the reference 2-pass brute-force squared EDT to ~1 ulp per term:
//  - row pass stores packed u16 nearest-opposite-bit distances (fg low16,
//    bg high16; the half not matching the pixel's own bit is exactly 0;
//    sentinel d=1024 when the row has no opposite bit, 1024^2 = 2^20).
//  - column pass: exact integer min of d*d + r^2 (finite < 2^18; sentinel
//    sums >= 2^20 only win when every row is sentinel -> reference's 1e9).
//    Branchless window r<=2 is exact when best <= 9 (any r>=3 candidate >= 9);
//    otherwise an exact global column scan continues from r=3.
//    The reference's field = sqrt(D) then field^2 is used as D directly
//    (<= 1 ulp difference; tolerance is 1e-3).

#define HH 256
#define WW 256
#define BB 4
#define SENT 1024u
#define SENTP 0x04000400u

__device__ uint2 g_pack[BB][HH * WW];

// ---------------------------------------------------------------------------
// nearest opposite-valued bit in a 256-bit row mask
// ---------------------------------------------------------------------------
__device__ __forceinline__ int nearest_opp(const unsigned* __restrict__ w, int i,
                                           unsigned inv) {
    const int k = i >> 5, bpos = i & 31;
    unsigned m = (w[k] ^ inv) & (0xFFFFFFFFu >> (31 - bpos));
    int L = -1000000, kk = k;
    while (true) {
        if (m) { L = (kk << 5) + 31 - __clz(m); break; }
        if (--kk < 0) break;
        m = w[kk] ^ inv;
    }
    m = (w[k] ^ inv) & (0xFFFFFFFFu << bpos);
    int R = 1000000;
    kk = k;
    while (true) {
        if (m) { R = (kk << 5) + __ffs(m) - 1; break; }
        if (++kk > 7) break;
        m = w[kk] ^ inv;
    }
    return min(i - L, R - i);
}

// ---------------------------------------------------------------------------
// K1: row pass, 2 rows per block. grid=(128, 4), block=256. Also zeroes out.
// ---------------------------------------------------------------------------
__global__ __launch_bounds__(256) void k_rowpass(const float* __restrict__ mo,
                                                 const float* __restrict__ gt,
                                                 float* __restrict__ out) {
    const int rp = blockIdx.x;  // row pair
    const int b = blockIdx.y;
    const int t = threadIdx.x;

    __shared__ unsigned P[2][8], G[2][8];
    float m0[2], m1[2], gv[2];
    bool pb[2], gb[2];

#pragma unroll
    for (int k = 0; k < 2; ++k) {  // 6 independent LDGs in flight
        int r = rp * 2 + k;
        m0[k] = mo[((b * 2 + 0) * HH + r) * WW + t];
        m1[k] = mo[((b * 2 + 1) * HH + r) * WW + t];
        gv[k] = gt[(b * HH + r) * WW + t];
    }
#pragma unroll
    for (int k = 0; k < 2; ++k) {
        pb[k] = (m1[k] > m0[k]);  // argmax ties -> channel 0
        gb[k] = (gv[k] > 0.5f);
        unsigned bp = __ballot_sync(0xFFFFFFFFu, pb[k]);
        unsigned bg = __ballot_sync(0xFFFFFFFFu, gb[k]);
        if ((t & 31) == 0) {
            P[k][t >> 5] = bp;
            G[k][t >> 5] = bg;
        }
    }
    __syncthreads();

#pragma unroll
    for (int k = 0; k < 2; ++k) {
        int r = rp * 2 + k;
        int pd = nearest_opp(P[k], t, pb[k] ? 0xFFFFFFFFu : 0u);
        int gd = nearest_opp(G[k], t, gb[k] ? 0xFFFFFFFFu : 0u);
        unsigned ps = (pd > 255) ? SENT : (unsigned)pd;
        unsigned gs = (gd > 255) ? SENT : (unsigned)gd;
        uint2 o;
        o.x = pb[k] ? ps : (ps << 16);  // fg dist low16, bg dist high16
        o.y = gb[k] ? gs : (gs << 16);
        g_pack[b][r * WW + t] = o;
    }

    if (rp == 0 && b == 0 && t == 0) out[0] = 0.0f;
}

// ---------------------------------------------------------------------------
// rare exact extension beyond the r<=2 window (global column scan from r=3)
// ---------------------------------------------------------------------------
__device__ __noinline__ unsigned extend(const uint2* __restrict__ src, int i,
                                        int col, int sh, int useY,
                                        unsigned best) {
#pragma unroll 1
    for (int r = 3; r < 256; ++r) {
        unsigned rr = (unsigned)(r * r);
        if (rr >= best) break;
        int lo = i - r, hi = i + r;
        if (lo >= 0) {
            uint2 w = __ldg(&src[lo * WW + col]);
            unsigned d = ((useY ? w.y : w.x) >> sh) & 0xFFFFu;
            best = min(best, d * d + rr);
        }
        if (hi < 256) {
            uint2 w = __ldg(&src[hi * WW + col]);
            unsigned d = ((useY ? w.y : w.x) >> sh) & 0xFFFFu;
            best = min(best, d * d + rr);
        }
    }
    return best;
}

// ---------------------------------------------------------------------------
// per-pixel loss term from the column tile (tile stride 16 uint2, r<=2 window)
// ---------------------------------------------------------------------------
__device__ __forceinline__ float pixel_term(const uint2* __restrict__ tcol,
                                            int ti, const uint2* __restrict__ src,
                                            int i, int col) {
    uint2 v = tcol[ti * 16];
    bool pbit = (v.x & 0xFFFFu) != 0u;  // own-plane dist >= 1 iff bit set
    bool gbit = (v.y & 0xFFFFu) != 0u;
    int shp = pbit ? 0 : 16;
    int shg = gbit ? 0 : 16;

    unsigned bestP = 0xFFFFFFFFu, bestG = 0xFFFFFFFFu;
#pragma unroll
    for (int dr = -2; dr <= 2; ++dr) {
        uint2 w = tcol[(ti + dr) * 16];
        unsigned rr = (unsigned)(dr * dr);
        unsigned dp = (w.x >> shp) & 0xFFFFu;
        unsigned dg = (w.y >> shg) & 0xFFFFu;
        bestP = min(bestP, dp * dp + rr);
        bestG = min(bestG, dg * dg + rr);
    }
    if (bestP > 9u) bestP = extend(src, i, col, shp, 0, bestP);
    if (bestG > 9u) bestG = extend(src, i, col, shg, 1, bestG);

    float acc = 0.0f;
    if (pbit != gbit) {  // err == 1, else term is 0
        float pt = (bestP >= (1u << 20)) ? (pbit ? 1.0e9f : 0.0f)
                                         : (float)bestP;
        float gtv = (bestG >= (1u << 20)) ? (gbit ? 1.0e9f : 0.0f)
                                          : (float)bestG;
        acc = pt + gtv;
    }
    return acc;
}

// ---------------------------------------------------------------------------
// K2: column pass + fused loss. grid=(16 colgroups, 8 rowtiles, 4 batches)
// = 512 blocks, block=256, 32x16 output tile (2 px/thread), 36x16 smem tile.
// ---------------------------------------------------------------------------
__global__ __launch_bounds__(256) void k_colpass(float* __restrict__ out) {
    const int cg = blockIdx.x;  // 16-col group
    const int ry = blockIdx.y;
    const int b = blockIdx.z;
    const int t = threadIdx.x;
    const int base = ry * 32 - 2;

    __shared__ uint2 tile[36 * 16];  // 4.5 KB
    __shared__ float wsum[8];

    const uint2* src = g_pack[b];
#pragma unroll
    for (int k = 0; k < 3; ++k) {
        int idx = t + k * 256;
        if (idx < 576) {
            int grow = base + (idx >> 4), c2 = idx & 15;
            tile[idx] = ((unsigned)grow < 256u) ? src[grow * WW + cg * 16 + c2]
                                                : make_uint2(SENTP, SENTP);
        }
    }
    __syncthreads();

    const int c = t & 15;
    const int rb = t >> 4;  // 0..15
    const int col = cg * 16 + c;
    const uint2* tcol = tile + c;

    float acc = pixel_term(tcol, rb + 2, src, ry * 32 + rb, col) +
                pixel_term(tcol, rb + 18, src, ry * 32 + rb + 16, col);

    // deterministic block reduction, then one REDG add of the scaled partial
#pragma unroll
    for (int o = 16; o > 0; o >>= 1) acc += __shfl_down_sync(0xFFFFFFFFu, acc, o);
    if ((t & 31) == 0) wsum[t >> 5] = acc;
    __syncthreads();
    if (t == 0) {
        float s = 0.0f;
#pragma unroll
        for (int j = 0; j < 8; ++j) s += wsum[j];
        atomicAdd(out, s * (1.0f / 262144.0f));
    }
}

extern "C" void kernel_launch(void* const* d_in, const int* in_sizes, int n_in,
                              void* d_out, int out_size) {
    const float* mo = (const float*)d_in[0];  // model_output (4,2,256,256) f32
    const float* gt = (const float*)d_in[1];  // ground_truth (4,1,256,256) f32
    float* out = (float*)d_out;

    dim3 grid1(128, BB);
    k_rowpass<<<grid1, 256>>>(mo, gt, out);
    dim3 grid2(16, 8, BB);
    k_colpass<<<grid2, 256>>>(out);
}

// round 12
// speedup vs baseline: 1.2657x; 1.2657x over previous
#include <cuda_runtime.h>

// HausdorffDTLoss: B=4, C=2, H=W=256, ALPHA=2.
// Matches the reference 2-pass brute-force squared EDT to ~1 ulp per term:
//  - row pass stores packed u16 nearest-opposite-bit distances (fg low16,
//    bg high16; the half not matching the pixel's own bit is exactly 0;
//    sentinel d=1024 when the row has no opposite bit, 1024^2 = 2^20).
//  - column pass: exact integer min of d*d + r^2 (finite < 2^18; sentinel
//    sums >= 2^20 only win when every row is sentinel -> reference's 1e9).
//    Branchless window r<=2 is exact when best <= 9 (any r>=3 candidate >= 9);
//    otherwise an exact global column scan continues from r=3.
//    field = sqrt(D) then field^2 is used as D directly (<=1 ulp; tol 1e-3).
// g_pack is padded with 2 all-sentinel rows on each side so the column-pass
// window needs no bounds handling and no shared-memory staging at all:
// each thread pulls its 5-row windows straight from global (L1-resident).

#define HH 256
#define WW 256
#define BB 4
#define SENT 1024u
#define SENTP 0x04000400u
#define PAD 2
#define ROWS_P (HH + 2 * PAD)

__device__ uint2 g_pack[BB][ROWS_P * WW];  // real row i lives at (i+PAD)

// ---------------------------------------------------------------------------
// nearest opposite-valued bit in a 256-bit row mask
// ---------------------------------------------------------------------------
__device__ __forceinline__ int nearest_opp(const unsigned* __restrict__ w, int i,
                                           unsigned inv) {
    const int k = i >> 5, bpos = i & 31;
    unsigned m = (w[k] ^ inv) & (0xFFFFFFFFu >> (31 - bpos));
    int L = -1000000, kk = k;
    while (true) {
        if (m) { L = (kk << 5) + 31 - __clz(m); break; }
        if (--kk < 0) break;
        m = w[kk] ^ inv;
    }
    m = (w[k] ^ inv) & (0xFFFFFFFFu << bpos);
    int R = 1000000;
    kk = k;
    while (true) {
        if (m) { R = (kk << 5) + __ffs(m) - 1; break; }
        if (++kk > 7) break;
        m = w[kk] ^ inv;
    }
    return min(i - L, R - i);
}

// ---------------------------------------------------------------------------
// K1: row pass, 2 rows per block. grid=(128, 4), block=256. Zeroes out and
// fills the sentinel pad rows.
// ---------------------------------------------------------------------------
__global__ __launch_bounds__(256) void k_rowpass(const float* __restrict__ mo,
                                                 const float* __restrict__ gt,
                                                 float* __restrict__ out) {
    const int rp = blockIdx.x;  // row pair
    const int b = blockIdx.y;
    const int t = threadIdx.x;

    __shared__ unsigned P[2][8], G[2][8];
    float m0[2], m1[2], gv[2];
    bool pb[2], gb[2];

#pragma unroll
    for (int k = 0; k < 2; ++k) {  // 6 independent LDGs in flight
        int r = rp * 2 + k;
        m0[k] = mo[((b * 2 + 0) * HH + r) * WW + t];
        m1[k] = mo[((b * 2 + 1) * HH + r) * WW + t];
        gv[k] = gt[(b * HH + r) * WW + t];
    }
#pragma unroll
    for (int k = 0; k < 2; ++k) {
        pb[k] = (m1[k] > m0[k]);  // argmax ties -> channel 0
        gb[k] = (gv[k] > 0.5f);
        unsigned bp = __ballot_sync(0xFFFFFFFFu, pb[k]);
        unsigned bg = __ballot_sync(0xFFFFFFFFu, gb[k]);
        if ((t & 31) == 0) {
            P[k][t >> 5] = bp;
            G[k][t >> 5] = bg;
        }
    }
    __syncthreads();

#pragma unroll
    for (int k = 0; k < 2; ++k) {
        int r = rp * 2 + k;
        int pd = nearest_opp(P[k], t, pb[k] ? 0xFFFFFFFFu : 0u);
        int gd = nearest_opp(G[k], t, gb[k] ? 0xFFFFFFFFu : 0u);
        unsigned ps = (pd > 255) ? SENT : (unsigned)pd;
        unsigned gs = (gd > 255) ? SENT : (unsigned)gd;
        uint2 o;
        o.x = pb[k] ? ps : (ps << 16);  // fg dist low16, bg dist high16
        o.y = gb[k] ? gs : (gs << 16);
        g_pack[b][(r + PAD) * WW + t] = o;
    }

    // pad rows (all-sentinel): rp 0 writes the top pair, rp 1 the bottom pair
    if (rp < 2) {
        int base = (rp == 0) ? 0 : (HH + PAD);
        g_pack[b][(base + 0) * WW + t] = make_uint2(SENTP, SENTP);
        g_pack[b][(base + 1) * WW + t] = make_uint2(SENTP, SENTP);
    }
    if (rp == 0 && b == 0 && t == 0) out[0] = 0.0f;
}

// ---------------------------------------------------------------------------
// rare exact extension beyond the r<=2 window (global column scan from r=3)
// ---------------------------------------------------------------------------
__device__ __noinline__ unsigned extend(const uint2* __restrict__ src, int i,
                                        int col, int sh, int useY,
                                        unsigned best) {
#pragma unroll 1
    for (int r = 3; r < 256; ++r) {
        unsigned rr = (unsigned)(r * r);
        if (rr >= best) break;
        int lo = i - r, hi = i + r;
        if (lo >= 0) {
            uint2 w = __ldg(&src[(lo + PAD) * WW + col]);
            unsigned d = ((useY ? w.y : w.x) >> sh) & 0xFFFFu;
            best = min(best, d * d + rr);
        }
        if (hi < 256) {
            uint2 w = __ldg(&src[(hi + PAD) * WW + col]);
            unsigned d = ((useY ? w.y : w.x) >> sh) & 0xFFFFu;
            best = min(best, d * d + rr);
        }
    }
    return best;
}

// ---------------------------------------------------------------------------
// per-pixel loss term from a 5-entry register window (w[2] = own row)
// ---------------------------------------------------------------------------
__device__ __forceinline__ float pixel_term(const uint2* __restrict__ w,
                                            const uint2* __restrict__ src,
                                            int i, int col) {
    uint2 v = w[2];
    bool pbit = (v.x & 0xFFFFu) != 0u;  // own-plane dist >= 1 iff bit set
    bool gbit = (v.y & 0xFFFFu) != 0u;
    int shp = pbit ? 0 : 16;
    int shg = gbit ? 0 : 16;

    unsigned bestP = 0xFFFFFFFFu, bestG = 0xFFFFFFFFu;
#pragma unroll
    for (int j = 0; j < 5; ++j) {
        unsigned rr = (unsigned)((j - 2) * (j - 2));
        unsigned dp = (w[j].x >> shp) & 0xFFFFu;
        unsigned dg = (w[j].y >> shg) & 0xFFFFu;
        bestP = min(bestP, dp * dp + rr);
        bestG = min(bestG, dg * dg + rr);
    }
    if (bestP > 9u) bestP = extend(src, i, col, shp, 0, bestP);
    if (bestG > 9u) bestG = extend(src, i, col, shg, 1, bestG);

    float acc = 0.0f;
    if (pbit != gbit) {  // err == 1, else term is 0
        float pt = (bestP >= (1u << 20)) ? (pbit ? 1.0e9f : 0.0f)
                                         : (float)bestP;
        float gtv = (bestG >= (1u << 20)) ? (gbit ? 1.0e9f : 0.0f)
                                          : (float)bestG;
        acc = pt + gtv;
    }
    return acc;
}

// ---------------------------------------------------------------------------
// K2: column pass + fused loss, NO shared-memory staging.
// grid=(16 colgroups, 8 rowtiles, 4 batches) = 512 blocks, block=256,
// 2 pixels/thread, 5-row windows loaded directly from (padded) global.
// ---------------------------------------------------------------------------
__global__ __launch_bounds__(256) void k_colpass(float* __restrict__ out) {
    const int cg = blockIdx.x;  // 16-col group
    const int ry = blockIdx.y;
    const int b = blockIdx.z;
    const int t = threadIdx.x;

    const int c = t & 15;
    const int rb = t >> 4;  // 0..15
    const int col = cg * 16 + c;
    const int i0 = ry * 32 + rb;       // pixel A row
    const int i1 = i0 + 16;            // pixel B row

    const uint2* src = g_pack[b];
    const uint2* p0 = src + (i0 - 2 + PAD) * WW + col;
    const uint2* p1 = src + (i1 - 2 + PAD) * WW + col;

    uint2 wa[5], wb[5];
#pragma unroll
    for (int j = 0; j < 5; ++j) wa[j] = __ldg(&p0[j * WW]);  // 10 LDGs in flight
#pragma unroll
    for (int j = 0; j < 5; ++j) wb[j] = __ldg(&p1[j * WW]);

    float acc = pixel_term(wa, src, i0, col) + pixel_term(wb, src, i1, col);

    // deterministic block reduction, then one REDG add of the scaled partial
    __shared__ float wsum[8];
#pragma unroll
    for (int o = 16; o > 0; o >>= 1) acc += __shfl_down_sync(0xFFFFFFFFu, acc, o);
    if ((t & 31) == 0) wsum[t >> 5] = acc;
    __syncthreads();
    if (t == 0) {
        float s = 0.0f;
#pragma unroll
        for (int j = 0; j < 8; ++j) s += wsum[j];
        atomicAdd(out, s * (1.0f / 262144.0f));
    }
}

extern "C" void kernel_launch(void* const* d_in, const int* in_sizes, int n_in,
                              void* d_out, int out_size) {
    const float* mo = (const float*)d_in[0];  // model_output (4,2,256,256) f32
    const float* gt = (const float*)d_in[1];  // ground_truth (4,1,256,256) f32
    float* out = (float*)d_out;

    dim3 grid1(128, BB);
    k_rowpass<<<grid1, 256>>>(mo, gt, out);
    dim3 grid2(16, 8, BB);
    k_colpass<<<grid2, 256>>>(out);
}